// round 2
// baseline (speedup 1.0000x reference)
#include <cuda_runtime.h>

#define BB 8
#define NN 2048
#define FIN 128
#define ODIM 256
#define NROWS (BB*NN)

// scratch (static device arrays — no allocation)
__device__ __align__(16) float g_T[NROWS * ODIM];   // X @ W^T  (16 MB)
__device__ __align__(16) float g_src[NROWS * 12];   // per row: -src[4], exp(src)[4], exp(0.2src)[4]
__device__ __align__(16) float g_dst[NROWS * 4];    // per row: dst[4]

// ---------------------------------------------------------------------------
// Kernel 1: T = X @ W^T   (M=16384, N=256, K=128), fp32 with packed fma.rn.f32x2
// ---------------------------------------------------------------------------
#define WS_STR 132
#define GEMM_SMEM ((128*128 + 128*WS_STR) * 4)

__global__ __launch_bounds__(256) void gemm_kernel(const float* __restrict__ X,
                                                   const float* __restrict__ W) {
    extern __shared__ float sm[];
    float* Xs = sm;                 // [128][128]  row-major (m, k)
    float* Ws = sm + 128 * 128;     // [k][o] transposed, stride WS_STR
    const int tid = threadIdx.x;
    const int m0 = blockIdx.y * 128;
    const int c0 = blockIdx.x * 128;

    // load X tile (coalesced float4 copy)
    {
        const float4* Xg = (const float4*)(X + (size_t)m0 * FIN);
        float4* Xs4 = (float4*)Xs;
#pragma unroll
        for (int i = 0; i < 16; i++) Xs4[tid + i * 256] = Xg[tid + i * 256];
    }
    // load W tile transposed: W[c0+o][k] -> Ws[k][o]   (scalar, coalesced along k)
    {
        const int l = tid & 31, wp = tid >> 5;
#pragma unroll
        for (int t = 0; t < 16; t++) {
            int o = wp * 16 + t;
            const float* wr = W + (size_t)(c0 + o) * FIN;
#pragma unroll
            for (int c = 0; c < 4; c++) {
                int k = l + 32 * c;
                Ws[k * WS_STR + o] = wr[k];
            }
        }
    }
    __syncthreads();

    const int tx = tid & 15, ty = tid >> 4;
    const int r0 = ty * 8, cc = tx * 8;

    unsigned long long acc[8][4];
#pragma unroll
    for (int i = 0; i < 8; i++)
#pragma unroll
        for (int j = 0; j < 4; j++) acc[i][j] = 0ull;   // (+0.f, +0.f)

#pragma unroll 2
    for (int k0 = 0; k0 < 128; k0 += 4) {
        float4 av[8];
#pragma unroll
        for (int i = 0; i < 8; i++)
            av[i] = *(const float4*)&Xs[(r0 + i) * 128 + k0];
#pragma unroll
        for (int kk = 0; kk < 4; kk++) {
            const float* wrow = &Ws[(k0 + kk) * WS_STR + cc];
            ulonglong2 b01 = *(const ulonglong2*)wrow;
            ulonglong2 b23 = *(const ulonglong2*)(wrow + 4);
            unsigned long long bp0 = b01.x, bp1 = b01.y, bp2 = b23.x, bp3 = b23.y;
#pragma unroll
            for (int i = 0; i < 8; i++) {
                float a = (kk == 0) ? av[i].x : (kk == 1) ? av[i].y : (kk == 2) ? av[i].z : av[i].w;
                unsigned long long a2;
                asm("mov.b64 %0, {%1, %1};" : "=l"(a2) : "f"(a));
                asm("fma.rn.f32x2 %0, %1, %2, %0;" : "+l"(acc[i][0]) : "l"(a2), "l"(bp0));
                asm("fma.rn.f32x2 %0, %1, %2, %0;" : "+l"(acc[i][1]) : "l"(a2), "l"(bp1));
                asm("fma.rn.f32x2 %0, %1, %2, %0;" : "+l"(acc[i][2]) : "l"(a2), "l"(bp2));
                asm("fma.rn.f32x2 %0, %1, %2, %0;" : "+l"(acc[i][3]) : "l"(a2), "l"(bp3));
            }
        }
    }

#pragma unroll
    for (int i = 0; i < 8; i++) {
        unsigned long long* Tp =
            (unsigned long long*)(g_T + (size_t)(m0 + r0 + i) * ODIM + c0 + cc);
#pragma unroll
        for (int j = 0; j < 4; j++) Tp[j] = acc[i][j];
    }
}

// ---------------------------------------------------------------------------
// Kernel 2: per-row src/dst projections + exps. One warp per row.
// ---------------------------------------------------------------------------
__global__ __launch_bounds__(256) void prep_kernel(const float* __restrict__ asrc,
                                                   const float* __restrict__ adst) {
    __shared__ float sa[256], sd[256];
    const int tid = threadIdx.x;
    sa[tid] = asrc[tid];
    sd[tid] = adst[tid];
    __syncthreads();

    const int l = tid & 31, w = tid >> 5;
    const int row = blockIdx.x * 8 + w;

    float s[4] = {0.f, 0.f, 0.f, 0.f}, d[4] = {0.f, 0.f, 0.f, 0.f};
    const float* Tr = g_T + (size_t)row * ODIM;
#pragma unroll
    for (int k = 0; k < 8; k++) {
        int e = k * 32 + l;          // element index 0..255; head = e/64 = k>>1
        float v = Tr[e];
        s[k >> 1] += v * sa[e];
        d[k >> 1] += v * sd[e];
    }
#pragma unroll
    for (int off = 16; off; off >>= 1) {
#pragma unroll
        for (int h = 0; h < 4; h++) {
            s[h] += __shfl_xor_sync(0xffffffffu, s[h], off);
            d[h] += __shfl_xor_sync(0xffffffffu, d[h], off);
        }
    }
    if (l == 0) {
#pragma unroll
        for (int h = 0; h < 4; h++) {
            g_src[row * 12 + h]     = -s[h];
            g_src[row * 12 + 4 + h] = expf(s[h]);
            g_src[row * 12 + 8 + h] = expf(0.2f * s[h]);
            g_dst[row * 4 + h]      = d[h];
        }
    }
}

// ---------------------------------------------------------------------------
// Kernel 3: masked softmax-diagonal scan over A + fused output scaling.
// Block = 256 thr (8 warps), each warp owns 4 rows; lanes stream j.
// smem: per-j tables dst / exp(dst) / exp(0.2 dst), 96 KB, 2 blocks/SM.
// ---------------------------------------------------------------------------
#define SCAN_SMEM (3 * NN * 4 * 4)

#define ACC1(AP, AN, A_, D_, NS_, P_, Q_)                                   \
    asm("{ .reg .pred p;\n\t"                                               \
        "setp.ge.f32 p, %3, %4;\n\t"                                        \
        "@p  fma.rn.f32 %0, %2, %5, %0;\n\t"                                \
        "@!p fma.rn.f32 %1, %2, %6, %1; }"                                  \
        : "+f"(AP), "+f"(AN)                                                \
        : "f"(A_), "f"(D_), "f"(NS_), "f"(P_), "f"(Q_))

__global__ __launch_bounds__(256, 2) void scan_kernel(const float* __restrict__ A,
                                                      float* __restrict__ out) {
    extern __shared__ float sm[];
    float4* sdst = (float4*)sm;               // [NN]
    float4* spd  = (float4*)(sm + NN * 4);    // exp(dst)
    float4* sqd  = (float4*)(sm + NN * 8);    // exp(0.2 dst)
    const int tid = threadIdx.x;
    const int b = blockIdx.y;
    const int l = tid & 31;
    const int r0 = blockIdx.x * 32 + (tid >> 5) * 4;   // row base within batch

    // prologue: load dst table for this batch, compute exps into smem
    {
        const float4* gd = (const float4*)(g_dst + (size_t)b * NN * 4);
        for (int t = tid; t < NN; t += 256) {
            float4 dv = gd[t];
            sdst[t] = dv;
            spd[t] = make_float4(__expf(dv.x), __expf(dv.y), __expf(dv.z), __expf(dv.w));
            sqd[t] = make_float4(__expf(0.2f * dv.x), __expf(0.2f * dv.y),
                                 __expf(0.2f * dv.z), __expf(0.2f * dv.w));
        }
    }
    __syncthreads();

    float ns[4][4];
#pragma unroll
    for (int ii = 0; ii < 4; ii++)
#pragma unroll
        for (int h = 0; h < 4; h++)
            ns[ii][h] = g_src[(size_t)(b * NN + r0 + ii) * 12 + h];

    const float* Ar[4];
#pragma unroll
    for (int ii = 0; ii < 4; ii++)
        Ar[ii] = A + ((size_t)b * NN + (r0 + ii)) * NN;

    float ap[4][4], an[4][4];
#pragma unroll
    for (int ii = 0; ii < 4; ii++)
#pragma unroll
        for (int h = 0; h < 4; h++) { ap[ii][h] = 0.f; an[ii][h] = 0.f; }

    // software-pipelined scan over all j (lane l covers j = l + 32*jt)
    float a[4];
#pragma unroll
    for (int ii = 0; ii < 4; ii++) a[ii] = Ar[ii][l];

    int j = l;
    for (int jt = 0; jt < 64; jt++) {
        float4 dv = sdst[j];
        float4 pv = spd[j];
        float4 qv = sqd[j];
        int jn = (jt == 63) ? j : j + 32;   // clamp to avoid OOB prefetch
        float anx[4];
#pragma unroll
        for (int ii = 0; ii < 4; ii++) anx[ii] = Ar[ii][jn];
#pragma unroll
        for (int ii = 0; ii < 4; ii++) {
            ACC1(ap[ii][0], an[ii][0], a[ii], dv.x, ns[ii][0], pv.x, qv.x);
            ACC1(ap[ii][1], an[ii][1], a[ii], dv.y, ns[ii][1], pv.y, qv.y);
            ACC1(ap[ii][2], an[ii][2], a[ii], dv.z, ns[ii][2], pv.z, qv.z);
            ACC1(ap[ii][3], an[ii][3], a[ii], dv.w, ns[ii][3], pv.w, qv.w);
        }
#pragma unroll
        for (int ii = 0; ii < 4; ii++) a[ii] = anx[ii];
        j = jn;
    }

    // warp reduction (all lanes end with full sums)
#pragma unroll
    for (int off = 16; off; off >>= 1)
#pragma unroll
        for (int ii = 0; ii < 4; ii++)
#pragma unroll
            for (int h = 0; h < 4; h++) {
                ap[ii][h] += __shfl_xor_sync(0xffffffffu, ap[ii][h], off);
                an[ii][h] += __shfl_xor_sync(0xffffffffu, an[ii][h], off);
            }

    const float* sdstf = sm;
    const float* spdf  = sm + NN * 4;
    const float* sqdf  = sm + NN * 8;

#pragma unroll
    for (int ii = 0; ii < 4; ii++) {
        const int il = r0 + ii;
        const size_t grow = (size_t)b * NN + il;
        float diag[4];
#pragma unroll
        for (int h = 0; h < 4; h++) {
            float ps = g_src[grow * 12 + 4 + h];
            float qs = g_src[grow * 12 + 8 + h];
            float denom = ps * ap[ii][h] + qs * an[ii][h];
            float dsth = sdstf[il * 4 + h];
            float num = (dsth >= ns[ii][h]) ? ps * spdf[il * 4 + h]
                                            : qs * sqdf[il * 4 + h];
            diag[h] = num / denom;
        }
        const float4* Tr = (const float4*)(g_T + grow * ODIM);
        float4* Or = (float4*)(out + grow * ODIM);
        float4 t0 = Tr[l];        // floats 4l..4l+3      -> head l>>4
        float4 t1 = Tr[32 + l];   // floats 128+4l..      -> head 2+(l>>4)
        float d0 = diag[l >> 4], d1 = diag[2 + (l >> 4)];
        Or[l]      = make_float4(t0.x * d0, t0.y * d0, t0.z * d0, t0.w * d0);
        Or[32 + l] = make_float4(t1.x * d1, t1.y * d1, t1.z * d1, t1.w * d1);
    }
}

// ---------------------------------------------------------------------------
extern "C" void kernel_launch(void* const* d_in, const int* in_sizes, int n_in,
                              void* d_out, int out_size) {
    const float* A    = (const float*)d_in[0];
    const float* X    = (const float*)d_in[1];
    const float* W    = (const float*)d_in[2];
    const float* asrc = (const float*)d_in[3];
    const float* adst = (const float*)d_in[4];
    float* out = (float*)d_out;

    cudaFuncSetAttribute(gemm_kernel, cudaFuncAttributeMaxDynamicSharedMemorySize, GEMM_SMEM);
    cudaFuncSetAttribute(scan_kernel, cudaFuncAttributeMaxDynamicSharedMemorySize, SCAN_SMEM);

    gemm_kernel<<<dim3(2, 128), 256, GEMM_SMEM>>>(X, W);
    prep_kernel<<<NROWS / 8, 256>>>(asrc, adst);
    scan_kernel<<<dim3(NN / 32, BB), 256, SCAN_SMEM>>>(A, out);
}